// round 14
// baseline (speedup 1.0000x reference)
#include <cuda_runtime.h>
#include <cuda_fp16.h>
#include <math.h>

#define NB   4
#define SEQ  4096
#define EDIM 1024
#define ADIM 64
#define NS   8      // KV splits per q-tile

// Projected Q,K,V stored as split fp16 planes (hi + lo), [B*S, A] each.
// (V lo plane still produced by projection; attention uses only Vh.)
__device__ __half g_Qh[NB * SEQ * ADIM];
__device__ __half g_Ql[NB * SEQ * ADIM];
__device__ __half g_Kh[NB * SEQ * ADIM];
__device__ __half g_Kl[NB * SEQ * ADIM];
__device__ __half g_Vh[NB * SEQ * ADIM];
__device__ __half g_Vl[NB * SEQ * ADIM];

// Split-KV partial results: O (unnormalized), row max m, row sum l.
__device__ float g_Om[NB * NS * SEQ * ADIM];   // 33.6 MB
__device__ float g_m [NB * NS * SEQ];
__device__ float g_l [NB * NS * SEQ];

// m16n8k16 f16 MMA, f32 accumulate, in-place C.
__device__ __forceinline__ void mma16816(float d[4], const unsigned a[4], const unsigned* b)
{
    asm volatile(
        "mma.sync.aligned.m16n8k16.row.col.f32.f16.f16.f32 "
        "{%0,%1,%2,%3}, {%4,%5,%6,%7}, {%8,%9}, {%0,%1,%2,%3};\n"
        : "+f"(d[0]), "+f"(d[1]), "+f"(d[2]), "+f"(d[3])
        : "r"(a[0]), "r"(a[1]), "r"(a[2]), "r"(a[3]), "r"(b[0]), "r"(b[1]));
}

// ldmatrix x4: 4 8x8 b16 matrices -> 4 regs/thread.
__device__ __forceinline__ void ldmx4(unsigned r[4], unsigned saddr)
{
    asm volatile(
        "ldmatrix.sync.aligned.m8n8.x4.shared.b16 {%0,%1,%2,%3}, [%4];\n"
        : "=r"(r[0]), "=r"(r[1]), "=r"(r[2]), "=r"(r[3]) : "r"(saddr));
}

// ldmatrix x4 transposed (for V^T fragments from row-major V).
__device__ __forceinline__ void ldmx4t(unsigned r[4], unsigned saddr)
{
    asm volatile(
        "ldmatrix.sync.aligned.m8n8.x4.trans.shared.b16 {%0,%1,%2,%3}, [%4];\n"
        : "=r"(r[0]), "=r"(r[1]), "=r"(r[2]), "=r"(r[3]) : "r"(saddr));
}

__device__ __forceinline__ void split1(float v, __half& h, __half& l)
{
    h = __float2half_rn(v);
    l = __float2half_rn(v - __half2float(h));
}

__device__ __forceinline__ void split2(float a, float b, unsigned& hi, unsigned& lo)
{
    __half2 h = __floats2half2_rn(a, b);
    float2 hf = __half22float2(h);
    __half2 l = __floats2half2_rn(a - hf.x, b - hf.y);
    hi = *(unsigned*)&h;
    lo = *(unsigned*)&l;
}

// Split 8 consecutive floats (two float4) into packed hi/lo uint4s.
__device__ __forceinline__ void split8(float4 a, float4 b, uint4& hi, uint4& lo)
{
    __half h[8], l[8];
    split1(a.x, h[0], l[0]); split1(a.y, h[1], l[1]);
    split1(a.z, h[2], l[2]); split1(a.w, h[3], l[3]);
    split1(b.x, h[4], l[4]); split1(b.y, h[5], l[5]);
    split1(b.z, h[6], l[6]); split1(b.w, h[7], l[7]);
    hi = *(uint4*)h;
    lo = *(uint4*)l;
}

// 16-byte async copy global -> shared (cp.async.cg).
__device__ __forceinline__ void cp16(void* smem_dst, const void* gsrc)
{
    unsigned sa = (unsigned)__cvta_generic_to_shared(smem_dst);
    asm volatile("cp.async.cg.shared.global [%0], [%1], 16;\n" :: "r"(sa), "l"(gsrc));
}

// ---------------------------------------------------------------------------
// QKV projection. X via cp.async double-buffer; W via direct LDG (L2-hot).
// Split stage uses contiguous-8 layout: each thread splits 8 consecutive
// elements of one row -> STS.128 stores (half the store instructions).
// Warp grid 2 rg x 4 cg (32 rows x 48 cols per warp).
// Smem (bytes): Xraw[2][2048]f32 @0, Xh[64][40] @16384, Xl @21504,
//               Wh[192][40] @26624, Wl @41984; total 57344.
// ---------------------------------------------------------------------------
#define QP_SMEM 57344

__global__ __launch_bounds__(256, 2)
void qkv_proj(const float* __restrict__ x,
              const float* __restrict__ wk,
              const float* __restrict__ wq,
              const float* __restrict__ wv)
{
    extern __shared__ __align__(16) char qsm[];
    float*  Xraw = (float*)qsm;                    // [2][2048]
    __half* Xh   = (__half*)(qsm + 16384);         // [64][40]
    __half* Xl   = (__half*)(qsm + 21504);
    __half* Wh   = (__half*)(qsm + 26624);         // [192][40]
    __half* Wl   = (__half*)(qsm + 41984);

    const int tid  = threadIdx.x;
    const int warp = tid >> 5;
    const int lane = tid & 31;
    const int g    = lane >> 2;
    const int cq   = lane & 3;
    const int li   = lane & 7;
    const int lm   = lane >> 3;
    const int rg   = warp >> 2;          // row group 0..1 (32 rows)
    const int cg   = warp & 3;           // col group 0..3 (48 cols)
    const int rows0 = blockIdx.x * 64;

    const int xr  = tid >> 3;            // staging copy: rows xr, xr+32
    const int xc  = (tid & 7) * 4;
    const int sr  = tid >> 2;            // split: row 0..63
    const int sc  = (tid & 3) * 8;       // split: 8 consecutive floats

    const unsigned aXh = (unsigned)__cvta_generic_to_shared(Xh)
                       + ((32 * rg + 8 * (lm & 1) + li) * 40 + 8 * (lm >> 1)) * 2;
    const unsigned aXl = aXh + 5120;
    const unsigned aWh = (unsigned)__cvta_generic_to_shared(Wh)
                       + ((cg * 48 + 8 * (lm >> 1) + li) * 40 + 8 * (lm & 1)) * 2;
    const unsigned aWl = aWh + 15360;

    // W row sources: matrix k supplies plane rows 64k + sr.
    const float* wsrc[3] = {
        wk + (size_t)sr * EDIM + sc,
        wq + (size_t)sr * EDIM + sc,
        wv + (size_t)sr * EDIM + sc
    };

    float acc[2][6][4];
    #pragma unroll
    for (int m = 0; m < 2; m++)
        #pragma unroll
        for (int j = 0; j < 6; j++)
            #pragma unroll
            for (int i = 0; i < 4; i++) acc[m][j][i] = 0.f;

    cp16(Xraw + xr * 32 + xc,        x + (size_t)(rows0 + xr) * EDIM + xc);
    cp16(Xraw + (xr + 32) * 32 + xc, x + (size_t)(rows0 + xr + 32) * EDIM + xc);
    asm volatile("cp.async.commit_group;\n" ::: "memory");

    for (int it = 0; it < 32; it++) {
        const int buf = it & 1;
        const int e0  = it * 32;
        float* Xb = Xraw + buf * 2048;

        // W prefetch into registers (L2-hot): 3 rows x 8 floats
        float4 wa[3], wb[3];
        #pragma unroll
        for (int k = 0; k < 3; k++) {
            wa[k] = *(const float4*)(wsrc[k] + e0);
            wb[k] = *(const float4*)(wsrc[k] + e0 + 4);
        }

        if (it + 1 < 32) {
            const int nbuf = (it + 1) & 1;
            const int e1   = (it + 1) * 32;
            float* Xn = Xraw + nbuf * 2048;
            cp16(Xn + xr * 32 + xc,        x + (size_t)(rows0 + xr) * EDIM + e1 + xc);
            cp16(Xn + (xr + 32) * 32 + xc, x + (size_t)(rows0 + xr + 32) * EDIM + e1 + xc);
            asm volatile("cp.async.commit_group;\n" ::: "memory");
            asm volatile("cp.async.wait_group 1;\n" ::: "memory");
        } else {
            asm volatile("cp.async.wait_group 0;\n" ::: "memory");
        }
        __syncthreads();   // prev MMA done with planes; X chunk `it` resident

        // split W registers -> planes (STS.128)
        #pragma unroll
        for (int k = 0; k < 3; k++) {
            uint4 hi, lo;
            split8(wa[k], wb[k], hi, lo);
            int r = 64 * k + sr;
            *(uint4*)(Wh + r * 40 + sc) = hi;
            *(uint4*)(Wl + r * 40 + sc) = lo;
        }
        // split X raw -> planes (one row of 8 per thread)
        {
            float4 a = *(const float4*)(Xb + sr * 32 + sc);
            float4 b = *(const float4*)(Xb + sr * 32 + sc + 4);
            uint4 hi, lo;
            split8(a, b, hi, lo);
            *(uint4*)(Xh + sr * 40 + sc) = hi;
            *(uint4*)(Xl + sr * 40 + sc) = lo;
        }
        __syncthreads();

        // MMAs
        #pragma unroll
        for (int kc = 0; kc < 2; kc++) {
            unsigned ah[2][4], al[2][4];
            #pragma unroll
            for (int m = 0; m < 2; m++) {
                ldmx4(ah[m], aXh + m * 1280 + kc * 32);
                ldmx4(al[m], aXl + m * 1280 + kc * 32);
            }
            #pragma unroll
            for (int t = 0; t < 3; t++) {
                unsigned bh[4], bl[4];
                ldmx4(bh, aWh + t * 1280 + kc * 32);
                ldmx4(bl, aWl + t * 1280 + kc * 32);
                #pragma unroll
                for (int m = 0; m < 2; m++) {
                    mma16816(acc[m][2 * t],     ah[m], bh);
                    mma16816(acc[m][2 * t],     ah[m], bl);
                    mma16816(acc[m][2 * t],     al[m], bh);
                    mma16816(acc[m][2 * t + 1], ah[m], bh + 2);
                    mma16816(acc[m][2 * t + 1], ah[m], bl + 2);
                    mma16816(acc[m][2 * t + 1], al[m], bh + 2);
                }
            }
        }
    }

    #pragma unroll
    for (int m = 0; m < 2; m++) {
        const int row_lo = rows0 + 32 * rg + 16 * m + g;
        const int row_hi = row_lo + 8;
        #pragma unroll
        for (int j = 0; j < 6; j++) {
            int colg = cg * 48 + 8 * j + 2 * cq;
            __half *dh, *dl;
            float sc2 = 1.f;
            int cl;
            if (colg < 64)       { dh = g_Kh; dl = g_Kl; cl = colg; }
            else if (colg < 128) { dh = g_Qh; dl = g_Ql; cl = colg - 64; sc2 = 0.125f; }
            else                 { dh = g_Vh; dl = g_Vl; cl = colg - 128; }

            unsigned h2, l2;
            split2(acc[m][j][0] * sc2, acc[m][j][1] * sc2, h2, l2);
            *(unsigned*)(dh + (size_t)row_lo * ADIM + cl) = h2;
            *(unsigned*)(dl + (size_t)row_lo * ADIM + cl) = l2;
            split2(acc[m][j][2] * sc2, acc[m][j][3] * sc2, h2, l2);
            *(unsigned*)(dh + (size_t)row_hi * ADIM + cl) = h2;
            *(unsigned*)(dl + (size_t)row_hi * ADIM + cl) = l2;
        }
    }
}

// ---------------------------------------------------------------------------
// Causal flash attention, split-KV (NS=8), q-tile = 128 rows (256 threads,
// 8 warps x 16 rows). K hi/lo split; V single fp16 plane. Each 64-key tile
// now serves 128 q-rows (half the tile-load traffic vs 64-row tiles).
// Causal mask applies on the two boundary tiles kb in {2qi, 2qi+1}.
// ---------------------------------------------------------------------------
#define ST 72
#define OFF_KH 0
#define OFF_KL 4608
#define OFF_VH 9216
#define SMEM_HALVES 13824

__global__ __launch_bounds__(256, 2)
void attn_kernel()
{
    extern __shared__ __align__(16) __half sh[];

    const int tid  = threadIdx.x;
    const int w    = tid >> 5;          // 0..7, warp owns q rows [16w,16w+16)
    const int lane = tid & 31;
    const int g    = lane >> 2;
    const int cq   = lane & 3;
    const int li   = lane & 7;
    const int lm   = lane >> 3;
    const int bx   = blockIdx.x;
    const int s    = bx & (NS - 1);
    const int qi   = (SEQ / 128 - 1) - (bx >> 3);   // heavy q-tiles first
    const int b    = blockIdx.y;
    const int q0   = qi * 128;
    const int kmax = 2 * qi + 1;

    if (s > kmax) return;

    const unsigned shu = (unsigned)__cvta_generic_to_shared(sh);
    const unsigned lrowK = ((8 * (lm >> 1) + li) * ST + 8 * (lm & 1)) * 2;
    const unsigned aKh = shu + OFF_KH * 2 + lrowK;
    const unsigned aKl = shu + OFF_KL * 2 + lrowK;
    const unsigned lrowV = ((8 * (lm & 1) + li) * ST + 8 * (lm >> 1)) * 2;
    const unsigned aVh = shu + OFF_VH * 2 + lrowV;

    unsigned qh[4][4], ql[4][4];
    {
        size_t rl = (size_t)(b * SEQ + q0 + 16 * w + g) * ADIM;
        size_t rh = rl + 8 * ADIM;
        #pragma unroll
        for (int kc = 0; kc < 4; kc++) {
            int off = 16 * kc + 2 * cq;
            qh[kc][0] = *(const unsigned*)(g_Qh + rl + off);
            qh[kc][1] = *(const unsigned*)(g_Qh + rh + off);
            qh[kc][2] = *(const unsigned*)(g_Qh + rl + off + 8);
            qh[kc][3] = *(const unsigned*)(g_Qh + rh + off + 8);
            ql[kc][0] = *(const unsigned*)(g_Ql + rl + off);
            ql[kc][1] = *(const unsigned*)(g_Ql + rh + off);
            ql[kc][2] = *(const unsigned*)(g_Ql + rl + off + 8);
            ql[kc][3] = *(const unsigned*)(g_Ql + rh + off + 8);
        }
    }

    float o[8][4];
    #pragma unroll
    for (int j = 0; j < 8; j++)
        #pragma unroll
        for (int i = 0; i < 4; i++) o[j][i] = 0.f;
    float m_lo = -1e30f, m_hi = -1e30f, l_lo = 0.f, l_hi = 0.f;

    for (int kb = s; kb <= kmax; kb += NS) {
        __syncthreads();
        {
            const __half* sKh = g_Kh + (size_t)(b * SEQ + kb * 64) * ADIM;
            const __half* sKl = g_Kl + (size_t)(b * SEQ + kb * 64) * ADIM;
            const __half* sVh = g_Vh + (size_t)(b * SEQ + kb * 64) * ADIM;
            #pragma unroll
            for (int k = 0; k < 2; k++) {
                int f = tid + 256 * k;
                int r = f >> 3, c = f & 7;
                *(uint4*)(sh + OFF_KH + r * ST + 8 * c) = *(const uint4*)(sKh + r * ADIM + 8 * c);
                *(uint4*)(sh + OFF_KL + r * ST + 8 * c) = *(const uint4*)(sKl + r * ADIM + 8 * c);
                *(uint4*)(sh + OFF_VH + r * ST + 8 * c) = *(const uint4*)(sVh + r * ADIM + 8 * c);
            }
        }
        __syncthreads();

        // ---- S = Q K^T
        float sreg[8][4];
        #pragma unroll
        for (int j = 0; j < 8; j++)
            #pragma unroll
            for (int i = 0; i < 4; i++) sreg[j][i] = 0.f;

        #pragma unroll
        for (int kc = 0; kc < 4; kc++) {
            #pragma unroll
            for (int t = 0; t < 4; t++) {
                unsigned bh[4], bl[4];
                ldmx4(bh, aKh + t * 2304 + kc * 32);
                ldmx4(bl, aKl + t * 2304 + kc * 32);
                mma16816(sreg[2 * t],     qh[kc], bh);
                mma16816(sreg[2 * t],     qh[kc], bl);
                mma16816(sreg[2 * t],     ql[kc], bh);
                mma16816(sreg[2 * t + 1], qh[kc], bh + 2);
                mma16816(sreg[2 * t + 1], qh[kc], bl + 2);
                mma16816(sreg[2 * t + 1], ql[kc], bh + 2);
            }
        }

        // ---- causal mask on boundary tiles (kb = 2qi or 2qi+1)
        if (kb >= 2 * qi) {
            int d    = (kb - 2 * qi) * 64;   // tile col offset relative to q0
            int r_lo = 16 * w + g, r_hi = r_lo + 8;
            #pragma unroll
            for (int j = 0; j < 8; j++) {
                int c0 = 8 * j + 2 * cq + d;
                if (c0     > r_lo) sreg[j][0] = -1e30f;
                if (c0 + 1 > r_lo) sreg[j][1] = -1e30f;
                if (c0     > r_hi) sreg[j][2] = -1e30f;
                if (c0 + 1 > r_hi) sreg[j][3] = -1e30f;
            }
        }

        // ---- online softmax
        float mx0 = -1e30f, mx1 = -1e30f;
        #pragma unroll
        for (int j = 0; j < 8; j++) {
            mx0 = fmaxf(mx0, fmaxf(sreg[j][0], sreg[j][1]));
            mx1 = fmaxf(mx1, fmaxf(sreg[j][2], sreg[j][3]));
        }
        mx0 = fmaxf(mx0, __shfl_xor_sync(0xffffffffu, mx0, 1));
        mx0 = fmaxf(mx0, __shfl_xor_sync(0xffffffffu, mx0, 2));
        mx1 = fmaxf(mx1, __shfl_xor_sync(0xffffffffu, mx1, 1));
        mx1 = fmaxf(mx1, __shfl_xor_sync(0xffffffffu, mx1, 2));
        float mn0 = fmaxf(m_lo, mx0), mn1 = fmaxf(m_hi, mx1);
        float sc0 = __expf(m_lo - mn0), sc1 = __expf(m_hi - mn1);
        m_lo = mn0; m_hi = mn1;
        float su0 = 0.f, su1 = 0.f;
        #pragma unroll
        for (int j = 0; j < 8; j++) {
            sreg[j][0] = __expf(sreg[j][0] - mn0);
            sreg[j][1] = __expf(sreg[j][1] - mn0);
            sreg[j][2] = __expf(sreg[j][2] - mn1);
            sreg[j][3] = __expf(sreg[j][3] - mn1);
            su0 += sreg[j][0] + sreg[j][1];
            su1 += sreg[j][2] + sreg[j][3];
        }
        su0 += __shfl_xor_sync(0xffffffffu, su0, 1);
        su0 += __shfl_xor_sync(0xffffffffu, su0, 2);
        su1 += __shfl_xor_sync(0xffffffffu, su1, 1);
        su1 += __shfl_xor_sync(0xffffffffu, su1, 2);
        l_lo = l_lo * sc0 + su0;
        l_hi = l_hi * sc1 + su1;
        #pragma unroll
        for (int j = 0; j < 8; j++) {
            o[j][0] *= sc0; o[j][1] *= sc0;
            o[j][2] *= sc1; o[j][3] *= sc1;
        }

        // ---- O += P V (P split, V single plane)
        #pragma unroll
        for (int kc = 0; kc < 4; kc++) {
            unsigned ph[4], pl[4];
            split2(sreg[2 * kc][0],     sreg[2 * kc][1],     ph[0], pl[0]);
            split2(sreg[2 * kc][2],     sreg[2 * kc][3],     ph[1], pl[1]);
            split2(sreg[2 * kc + 1][0], sreg[2 * kc + 1][1], ph[2], pl[2]);
            split2(sreg[2 * kc + 1][2], sreg[2 * kc + 1][3], ph[3], pl[3]);
            #pragma unroll
            for (int t = 0; t < 4; t++) {
                unsigned bh[4];
                ldmx4t(bh, aVh + kc * 2304 + t * 32);
                mma16816(o[2 * t],     ph, bh);
                mma16816(o[2 * t],     pl, bh);
                mma16816(o[2 * t + 1], ph, bh + 2);
                mma16816(o[2 * t + 1], pl, bh + 2);
            }
        }
    }

    const int row_lo = q0 + 16 * w + g;
    const int row_hi = row_lo + 8;
    const size_t sb  = (size_t)(b * NS + s) * SEQ;
    #pragma unroll
    for (int j = 0; j < 8; j++) {
        int col = 8 * j + 2 * cq;
        *(float2*)(g_Om + (sb + row_lo) * ADIM + col) = make_float2(o[j][0], o[j][1]);
        *(float2*)(g_Om + (sb + row_hi) * ADIM + col) = make_float2(o[j][2], o[j][3]);
    }
    if (cq == 0) {
        g_m[sb + row_lo] = m_lo;  g_l[sb + row_lo] = l_lo;
        g_m[sb + row_hi] = m_hi;  g_l[sb + row_hi] = l_hi;
    }
}

// ---------------------------------------------------------------------------
// Combine split-KV partials. ns per row = (row/64 + 1) capped at NS —
// unchanged: split s contributes to row r iff s <= r/64.
// ---------------------------------------------------------------------------
__global__ __launch_bounds__(128)
void combine_kernel(float* __restrict__ out)
{
    const int tid = threadIdx.x;
    const int row = blockIdx.x * 8 + (tid >> 4);
    const int b   = blockIdx.y;
    const int c0  = (tid & 15) * 4;
    const int qi  = row >> 6;
    const int ns  = (qi + 1 < NS) ? (qi + 1) : NS;

    float m = -1e30f;
    #pragma unroll
    for (int s = 0; s < NS; s++)
        if (s < ns) m = fmaxf(m, g_m[(size_t)(b * NS + s) * SEQ + row]);

    float l = 0.f;
    float4 acc = make_float4(0.f, 0.f, 0.f, 0.f);
    #pragma unroll
    for (int s = 0; s < NS; s++) {
        if (s >= ns) break;
        size_t sb = (size_t)(b * NS + s) * SEQ + row;
        float wgt = __expf(g_m[sb] - m);
        l += g_l[sb] * wgt;
        float4 v = *(const float4*)(g_Om + sb * ADIM + c0);
        acc.x += v.x * wgt; acc.y += v.y * wgt;
        acc.z += v.z * wgt; acc.w += v.w * wgt;
    }
    float inv = 1.f / l;
    float4 r;
    r.x = rintf(acc.x * inv * 1e4f) * 1e-4f;
    r.y = rintf(acc.y * inv * 1e4f) * 1e-4f;
    r.z = rintf(acc.z * inv * 1e4f) * 1e-4f;
    r.w = rintf(acc.w * inv * 1e4f) * 1e-4f;
    *(float4*)(out + ((size_t)b * SEQ + row) * ADIM + c0) = r;
}

extern "C" void kernel_launch(void* const* d_in, const int* in_sizes, int n_in,
                              void* d_out, int out_size)
{
    const float* x  = (const float*)d_in[0];
    const float* wk = (const float*)d_in[1];
    const float* wq = (const float*)d_in[2];
    const float* wv = (const float*)d_in[3];
    float* out = (float*)d_out;

    cudaFuncSetAttribute(qkv_proj, cudaFuncAttributeMaxDynamicSharedMemorySize, QP_SMEM);
    qkv_proj<<<256, 256, QP_SMEM>>>(x, wk, wq, wv);

    int smem = SMEM_HALVES * (int)sizeof(__half);  // 27648 B
    cudaFuncSetAttribute(attn_kernel, cudaFuncAttributeMaxDynamicSharedMemorySize, smem);
    attn_kernel<<<dim3((SEQ / 128) * NS, NB), 256, smem>>>();

    combine_kernel<<<dim3(SEQ / 8, NB), 128>>>(out);
}

// round 15
// speedup vs baseline: 1.1070x; 1.1070x over previous
#include <cuda_runtime.h>
#include <cuda_fp16.h>
#include <math.h>

#define NB   4
#define SEQ  4096
#define EDIM 1024
#define ADIM 64
#define NS   8      // KV splits per q-tile

// Projected Q,K,V stored as split fp16 planes (hi + lo), [B*S, A] each.
// (V lo plane still produced by projection; attention uses only Vh.)
__device__ __half g_Qh[NB * SEQ * ADIM];
__device__ __half g_Ql[NB * SEQ * ADIM];
__device__ __half g_Kh[NB * SEQ * ADIM];
__device__ __half g_Kl[NB * SEQ * ADIM];
__device__ __half g_Vh[NB * SEQ * ADIM];
__device__ __half g_Vl[NB * SEQ * ADIM];

// Split-KV partial results: O (unnormalized), row max m, row sum l.
__device__ float g_Om[NB * NS * SEQ * ADIM];   // 33.6 MB
__device__ float g_m [NB * NS * SEQ];
__device__ float g_l [NB * NS * SEQ];

// m16n8k16 f16 MMA, f32 accumulate, in-place C.
__device__ __forceinline__ void mma16816(float d[4], const unsigned a[4], const unsigned* b)
{
    asm volatile(
        "mma.sync.aligned.m16n8k16.row.col.f32.f16.f16.f32 "
        "{%0,%1,%2,%3}, {%4,%5,%6,%7}, {%8,%9}, {%0,%1,%2,%3};\n"
        : "+f"(d[0]), "+f"(d[1]), "+f"(d[2]), "+f"(d[3])
        : "r"(a[0]), "r"(a[1]), "r"(a[2]), "r"(a[3]), "r"(b[0]), "r"(b[1]));
}

// ldmatrix x4: 4 8x8 b16 matrices -> 4 regs/thread.
__device__ __forceinline__ void ldmx4(unsigned r[4], unsigned saddr)
{
    asm volatile(
        "ldmatrix.sync.aligned.m8n8.x4.shared.b16 {%0,%1,%2,%3}, [%4];\n"
        : "=r"(r[0]), "=r"(r[1]), "=r"(r[2]), "=r"(r[3]) : "r"(saddr));
}

// ldmatrix x4 transposed (for V^T fragments from row-major V).
__device__ __forceinline__ void ldmx4t(unsigned r[4], unsigned saddr)
{
    asm volatile(
        "ldmatrix.sync.aligned.m8n8.x4.trans.shared.b16 {%0,%1,%2,%3}, [%4];\n"
        : "=r"(r[0]), "=r"(r[1]), "=r"(r[2]), "=r"(r[3]) : "r"(saddr));
}

__device__ __forceinline__ void split1(float v, __half& h, __half& l)
{
    h = __float2half_rn(v);
    l = __float2half_rn(v - __half2float(h));
}

__device__ __forceinline__ void split2(float a, float b, unsigned& hi, unsigned& lo)
{
    __half2 h = __floats2half2_rn(a, b);
    float2 hf = __half22float2(h);
    __half2 l = __floats2half2_rn(a - hf.x, b - hf.y);
    hi = *(unsigned*)&h;
    lo = *(unsigned*)&l;
}

// 16-byte async copy global -> shared (cp.async.cg), generic dst.
__device__ __forceinline__ void cp16(void* smem_dst, const void* gsrc)
{
    unsigned sa = (unsigned)__cvta_generic_to_shared(smem_dst);
    asm volatile("cp.async.cg.shared.global [%0], [%1], 16;\n" :: "r"(sa), "l"(gsrc));
}

// 16-byte async copy global -> shared, u32 smem address.
__device__ __forceinline__ void cp16s(unsigned sa, const void* gsrc)
{
    asm volatile("cp.async.cg.shared.global [%0], [%1], 16;\n" :: "r"(sa), "l"(gsrc));
}

// ---------------------------------------------------------------------------
// QKV projection — exact R12/R10 version (measured 66.2us). X via cp.async
// double-buffer; W via direct LDG (L2-hot) + inline split. Warp grid 2x4.
// Smem (bytes): Xraw[2][2048]f32 @0, Xh[64][40] @16384, Xl @21504,
//               Wh[192][40] @26624, Wl @41984; total 57344.
// ---------------------------------------------------------------------------
#define QP_SMEM 57344

__global__ __launch_bounds__(256, 2)
void qkv_proj(const float* __restrict__ x,
              const float* __restrict__ wk,
              const float* __restrict__ wq,
              const float* __restrict__ wv)
{
    extern __shared__ __align__(16) char qsm[];
    float*  Xraw = (float*)qsm;                    // [2][2048]
    __half* Xh   = (__half*)(qsm + 16384);         // [64][40]
    __half* Xl   = (__half*)(qsm + 21504);
    __half* Wh   = (__half*)(qsm + 26624);         // [192][40]
    __half* Wl   = (__half*)(qsm + 41984);

    const int tid  = threadIdx.x;
    const int warp = tid >> 5;
    const int lane = tid & 31;
    const int g    = lane >> 2;
    const int cq   = lane & 3;
    const int li   = lane & 7;
    const int lm   = lane >> 3;
    const int rg   = warp >> 2;          // row group 0..1 (32 rows)
    const int cg   = warp & 3;           // col group 0..3 (48 cols)
    const int rows0 = blockIdx.x * 64;

    const int xr  = tid >> 3;            // 0..31
    const int xc  = (tid & 7) * 4;
    const int wr0 = tid >> 3;            // W rows wr0 + 32k

    const unsigned aXh = (unsigned)__cvta_generic_to_shared(Xh)
                       + ((32 * rg + 8 * (lm & 1) + li) * 40 + 8 * (lm >> 1)) * 2;
    const unsigned aXl = aXh + 5120;
    const unsigned aWh = (unsigned)__cvta_generic_to_shared(Wh)
                       + ((cg * 48 + 8 * (lm >> 1) + li) * 40 + 8 * (lm & 1)) * 2;
    const unsigned aWl = aWh + 15360;

    // Per-thread W row sources (constant across iterations)
    const float* wsrc[6];
    #pragma unroll
    for (int k = 0; k < 6; k++) {
        int r = wr0 + 32 * k;
        wsrc[k] = (r < 64)  ? wk + (size_t)r * EDIM
                : (r < 128) ? wq + (size_t)(r - 64) * EDIM
                            : wv + (size_t)(r - 128) * EDIM;
    }

    float acc[2][6][4];
    #pragma unroll
    for (int m = 0; m < 2; m++)
        #pragma unroll
        for (int j = 0; j < 6; j++)
            #pragma unroll
            for (int i = 0; i < 4; i++) acc[m][j][i] = 0.f;

    cp16(Xraw + xr * 32 + xc,        x + (size_t)(rows0 + xr) * EDIM + xc);
    cp16(Xraw + (xr + 32) * 32 + xc, x + (size_t)(rows0 + xr + 32) * EDIM + xc);
    asm volatile("cp.async.commit_group;\n" ::: "memory");

    for (int it = 0; it < 32; it++) {
        const int buf = it & 1;
        const int e0  = it * 32;
        float* Xb = Xraw + buf * 2048;

        // W prefetch into registers (L2-hot)
        float4 wvreg[6];
        #pragma unroll
        for (int k = 0; k < 6; k++)
            wvreg[k] = *(const float4*)(wsrc[k] + e0 + xc);

        if (it + 1 < 32) {
            const int nbuf = (it + 1) & 1;
            const int e1   = (it + 1) * 32;
            float* Xn = Xraw + nbuf * 2048;
            cp16(Xn + xr * 32 + xc,        x + (size_t)(rows0 + xr) * EDIM + e1 + xc);
            cp16(Xn + (xr + 32) * 32 + xc, x + (size_t)(rows0 + xr + 32) * EDIM + e1 + xc);
            asm volatile("cp.async.commit_group;\n" ::: "memory");
            asm volatile("cp.async.wait_group 1;\n" ::: "memory");
        } else {
            asm volatile("cp.async.wait_group 0;\n" ::: "memory");
        }
        __syncthreads();   // prev MMA done with planes; X chunk `it` resident

        // split W registers -> planes
        #pragma unroll
        for (int k = 0; k < 6; k++) {
            int r = wr0 + 32 * k;
            __half h[4], l[4];
            split1(wvreg[k].x, h[0], l[0]); split1(wvreg[k].y, h[1], l[1]);
            split1(wvreg[k].z, h[2], l[2]); split1(wvreg[k].w, h[3], l[3]);
            *(uint2*)(Wh + r * 40 + xc) = *(uint2*)h;
            *(uint2*)(Wl + r * 40 + xc) = *(uint2*)l;
        }
        // split X raw -> planes
        #pragma unroll
        for (int k = 0; k < 2; k++) {
            int r = xr + 32 * k;
            float4 v = *(const float4*)(Xb + r * 32 + xc);
            __half h[4], l[4];
            split1(v.x, h[0], l[0]); split1(v.y, h[1], l[1]);
            split1(v.z, h[2], l[2]); split1(v.w, h[3], l[3]);
            *(uint2*)(Xh + r * 40 + xc) = *(uint2*)h;
            *(uint2*)(Xl + r * 40 + xc) = *(uint2*)l;
        }
        __syncthreads();

        // MMAs
        #pragma unroll
        for (int kc = 0; kc < 2; kc++) {
            unsigned ah[2][4], al[2][4];
            #pragma unroll
            for (int m = 0; m < 2; m++) {
                ldmx4(ah[m], aXh + m * 1280 + kc * 32);
                ldmx4(al[m], aXl + m * 1280 + kc * 32);
            }
            #pragma unroll
            for (int t = 0; t < 3; t++) {
                unsigned bh[4], bl[4];
                ldmx4(bh, aWh + t * 1280 + kc * 32);
                ldmx4(bl, aWl + t * 1280 + kc * 32);
                #pragma unroll
                for (int m = 0; m < 2; m++) {
                    mma16816(acc[m][2 * t],     ah[m], bh);
                    mma16816(acc[m][2 * t],     ah[m], bl);
                    mma16816(acc[m][2 * t],     al[m], bh);
                    mma16816(acc[m][2 * t + 1], ah[m], bh + 2);
                    mma16816(acc[m][2 * t + 1], ah[m], bl + 2);
                    mma16816(acc[m][2 * t + 1], al[m], bh + 2);
                }
            }
        }
    }

    #pragma unroll
    for (int m = 0; m < 2; m++) {
        const int row_lo = rows0 + 32 * rg + 16 * m + g;
        const int row_hi = row_lo + 8;
        #pragma unroll
        for (int j = 0; j < 6; j++) {
            int colg = cg * 48 + 8 * j + 2 * cq;
            __half *dh, *dl;
            float sc = 1.f;
            int cl;
            if (colg < 64)       { dh = g_Kh; dl = g_Kl; cl = colg; }
            else if (colg < 128) { dh = g_Qh; dl = g_Ql; cl = colg - 64; sc = 0.125f; }
            else                 { dh = g_Vh; dl = g_Vl; cl = colg - 128; }

            unsigned h2, l2;
            split2(acc[m][j][0] * sc, acc[m][j][1] * sc, h2, l2);
            *(unsigned*)(dh + (size_t)row_lo * ADIM + cl) = h2;
            *(unsigned*)(dl + (size_t)row_lo * ADIM + cl) = l2;
            split2(acc[m][j][2] * sc, acc[m][j][3] * sc, h2, l2);
            *(unsigned*)(dh + (size_t)row_hi * ADIM + cl) = h2;
            *(unsigned*)(dl + (size_t)row_hi * ADIM + cl) = l2;
        }
    }
}

// ---------------------------------------------------------------------------
// Causal flash attention, split-KV (NS=8), 64-row q-tile (R12 layout) with
// cp.async DOUBLE-BUFFERED K/V tiles: tile i+1 streams in while tile i's
// MMAs run. K hi/lo split; V single fp16 plane.
// Stage = Kh[64][72] + Kl + Vh = 13824 halves (27648 B); 2 stages = 55296 B.
// ---------------------------------------------------------------------------
#define ST 72
#define OFF_KH 0
#define OFF_KL 4608
#define OFF_VH 9216
#define STAGE_HALVES 13824
#define STAGE_BYTES  27648
#define SMEM_ATTN    (2 * STAGE_BYTES)

__global__ __launch_bounds__(128, 4)
void attn_kernel()
{
    extern __shared__ __align__(16) __half sh[];

    const int tid  = threadIdx.x;
    const int w    = tid >> 5;
    const int lane = tid & 31;
    const int g    = lane >> 2;
    const int cq   = lane & 3;
    const int li   = lane & 7;
    const int lm   = lane >> 3;
    const int bx   = blockIdx.x;
    const int s    = bx & (NS - 1);
    const int qi   = (SEQ / 64 - 1) - (bx >> 3);
    const int b    = blockIdx.y;
    const int q0   = qi * 64;

    if (qi < s) return;

    const unsigned shu = (unsigned)__cvta_generic_to_shared(sh);
    const unsigned lrowK = ((8 * (lm >> 1) + li) * ST + 8 * (lm & 1)) * 2;
    const unsigned lrowV = ((8 * (lm & 1) + li) * ST + 8 * (lm >> 1)) * 2;

    // per-thread tile copy indices
    const int cr = tid >> 1;           // row 0..63
    const int cc = (tid & 1) * 32;     // half-offset 0 or 32 (16B each... 8 halves*?)
    // each thread copies 4 uint4 per array: rows via f = tid + 128k
    // (keep R12's pattern: f>>3 row, f&7 col-of-8)

    unsigned qh[4][4], ql[4][4];
    {
        size_t rl = (size_t)(b * SEQ + q0 + 16 * w + g) * ADIM;
        size_t rh = rl + 8 * ADIM;
        #pragma unroll
        for (int kc = 0; kc < 4; kc++) {
            int off = 16 * kc + 2 * cq;
            qh[kc][0] = *(const unsigned*)(g_Qh + rl + off);
            qh[kc][1] = *(const unsigned*)(g_Qh + rh + off);
            qh[kc][2] = *(const unsigned*)(g_Qh + rl + off + 8);
            qh[kc][3] = *(const unsigned*)(g_Qh + rh + off + 8);
            ql[kc][0] = *(const unsigned*)(g_Ql + rl + off);
            ql[kc][1] = *(const unsigned*)(g_Ql + rh + off);
            ql[kc][2] = *(const unsigned*)(g_Ql + rl + off + 8);
            ql[kc][3] = *(const unsigned*)(g_Ql + rh + off + 8);
        }
    }
    (void)cr; (void)cc;

    float o[8][4];
    #pragma unroll
    for (int j = 0; j < 8; j++)
        #pragma unroll
        for (int i = 0; i < 4; i++) o[j][i] = 0.f;
    float m_lo = -1e30f, m_hi = -1e30f, l_lo = 0.f, l_hi = 0.f;

    // ---- issue tile kb=s into stage 0
    {
        const __half* sKh = g_Kh + (size_t)(b * SEQ + s * 64) * ADIM;
        const __half* sKl = g_Kl + (size_t)(b * SEQ + s * 64) * ADIM;
        const __half* sVh = g_Vh + (size_t)(b * SEQ + s * 64) * ADIM;
        #pragma unroll
        for (int k = 0; k < 4; k++) {
            int f = tid + 128 * k;
            int r = f >> 3, c = f & 7;
            unsigned d = shu + (r * ST + 8 * c) * 2;
            const size_t gsrc = (size_t)r * ADIM + 8 * c;
            cp16s(d + OFF_KH * 2, sKh + gsrc);
            cp16s(d + OFF_KL * 2, sKl + gsrc);
            cp16s(d + OFF_VH * 2, sVh + gsrc);
        }
        asm volatile("cp.async.commit_group;\n" ::: "memory");
    }

    int stg = 0;
    for (int kb = s; kb <= qi; kb += NS) {
        // ---- prefetch next tile into the other stage (its consumer finished
        // at the trailing barrier of the previous iteration)
        if (kb + NS <= qi) {
            const unsigned sb2 = shu + (stg ^ 1) * STAGE_BYTES;
            const __half* sKh = g_Kh + (size_t)(b * SEQ + (kb + NS) * 64) * ADIM;
            const __half* sKl = g_Kl + (size_t)(b * SEQ + (kb + NS) * 64) * ADIM;
            const __half* sVh = g_Vh + (size_t)(b * SEQ + (kb + NS) * 64) * ADIM;
            #pragma unroll
            for (int k = 0; k < 4; k++) {
                int f = tid + 128 * k;
                int r = f >> 3, c = f & 7;
                unsigned d = sb2 + (r * ST + 8 * c) * 2;
                const size_t gsrc = (size_t)r * ADIM + 8 * c;
                cp16s(d + OFF_KH * 2, sKh + gsrc);
                cp16s(d + OFF_KL * 2, sKl + gsrc);
                cp16s(d + OFF_VH * 2, sVh + gsrc);
            }
            asm volatile("cp.async.commit_group;\n" ::: "memory");
            asm volatile("cp.async.wait_group 1;\n" ::: "memory");
        } else {
            asm volatile("cp.async.wait_group 0;\n" ::: "memory");
        }
        __syncthreads();   // current stage resident for all warps

        const unsigned sb = shu + stg * STAGE_BYTES;
        const unsigned aKh = sb + OFF_KH * 2 + lrowK;
        const unsigned aKl = sb + OFF_KL * 2 + lrowK;
        const unsigned aVh = sb + OFF_VH * 2 + lrowV;

        // ---- S = Q K^T
        float sreg[8][4];
        #pragma unroll
        for (int j = 0; j < 8; j++)
            #pragma unroll
            for (int i = 0; i < 4; i++) sreg[j][i] = 0.f;

        #pragma unroll
        for (int kc = 0; kc < 4; kc++) {
            #pragma unroll
            for (int t = 0; t < 4; t++) {
                unsigned bh[4], bl[4];
                ldmx4(bh, aKh + t * 2304 + kc * 32);
                ldmx4(bl, aKl + t * 2304 + kc * 32);
                mma16816(sreg[2 * t],     qh[kc], bh);
                mma16816(sreg[2 * t],     qh[kc], bl);
                mma16816(sreg[2 * t],     ql[kc], bh);
                mma16816(sreg[2 * t + 1], qh[kc], bh + 2);
                mma16816(sreg[2 * t + 1], qh[kc], bl + 2);
                mma16816(sreg[2 * t + 1], ql[kc], bh + 2);
            }
        }

        if (kb == qi) {
            int r_lo = 16 * w + g, r_hi = r_lo + 8;
            #pragma unroll
            for (int j = 0; j < 8; j++) {
                int c0 = 8 * j + 2 * cq;
                if (c0     > r_lo) sreg[j][0] = -1e30f;
                if (c0 + 1 > r_lo) sreg[j][1] = -1e30f;
                if (c0     > r_hi) sreg[j][2] = -1e30f;
                if (c0 + 1 > r_hi) sreg[j][3] = -1e30f;
            }
        }

        // ---- online softmax
        float mx0 = -1e30f, mx1 = -1e30f;
        #pragma unroll
        for (int j = 0; j < 8; j++) {
            mx0 = fmaxf(mx0, fmaxf(sreg[j][0], sreg[j][1]));
            mx1 = fmaxf(mx1, fmaxf(sreg[j][2], sreg[j][3]));
        }
        mx0 = fmaxf(mx0, __shfl_xor_sync(0xffffffffu, mx0, 1));
        mx0 = fmaxf(mx0, __shfl_xor_sync(0xffffffffu, mx0, 2));
        mx1 = fmaxf(mx1, __shfl_xor_sync(0xffffffffu, mx1, 1));
        mx1 = fmaxf(mx1, __shfl_xor_sync(0xffffffffu, mx1, 2));
        float mn0 = fmaxf(m_lo, mx0), mn1 = fmaxf(m_hi, mx1);
        float sc0 = __expf(m_lo - mn0), sc1 = __expf(m_hi - mn1);
        m_lo = mn0; m_hi = mn1;
        float su0 = 0.f, su1 = 0.f;
        #pragma unroll
        for (int j = 0; j < 8; j++) {
            sreg[j][0] = __expf(sreg[j][0] - mn0);
            sreg[j][1] = __expf(sreg[j][1] - mn0);
            sreg[j][2] = __expf(sreg[j][2] - mn1);
            sreg[j][3] = __expf(sreg[j][3] - mn1);
            su0 += sreg[j][0] + sreg[j][1];
            su1 += sreg[j][2] + sreg[j][3];
        }
        su0 += __shfl_xor_sync(0xffffffffu, su0, 1);
        su0 += __shfl_xor_sync(0xffffffffu, su0, 2);
        su1 += __shfl_xor_sync(0xffffffffu, su1, 1);
        su1 += __shfl_xor_sync(0xffffffffu, su1, 2);
        l_lo = l_lo * sc0 + su0;
        l_hi = l_hi * sc1 + su1;
        #pragma unroll
        for (int j = 0; j < 8; j++) {
            o[j][0] *= sc0; o[j][1] *= sc0;
            o[j][2] *= sc1; o[j][3] *= sc1;
        }

        // ---- O += P V (P split, V single plane)
        #pragma unroll
        for (int kc = 0; kc < 4; kc++) {
            unsigned ph[4], pl[4];
            split2(sreg[2 * kc][0],     sreg[2 * kc][1],     ph[0], pl[0]);
            split2(sreg[2 * kc][2],     sreg[2 * kc][3],     ph[1], pl[1]);
            split2(sreg[2 * kc + 1][0], sreg[2 * kc + 1][1], ph[2], pl[2]);
            split2(sreg[2 * kc + 1][2], sreg[2 * kc + 1][3], ph[3], pl[3]);
            #pragma unroll
            for (int t = 0; t < 4; t++) {
                unsigned bh[4];
                ldmx4t(bh, aVh + kc * 2304 + t * 32);
                mma16816(o[2 * t],     ph, bh);
                mma16816(o[2 * t],     pl, bh);
                mma16816(o[2 * t + 1], ph, bh + 2);
                mma16816(o[2 * t + 1], pl, bh + 2);
            }
        }

        __syncthreads();   // all warps done with stage `stg` before reuse
        stg ^= 1;
    }

    const int row_lo = q0 + 16 * w + g;
    const int row_hi = row_lo + 8;
    const size_t sb  = (size_t)(b * NS + s) * SEQ;
    #pragma unroll
    for (int j = 0; j < 8; j++) {
        int col = 8 * j + 2 * cq;
        *(float2*)(g_Om + (sb + row_lo) * ADIM + col) = make_float2(o[j][0], o[j][1]);
        *(float2*)(g_Om + (sb + row_hi) * ADIM + col) = make_float2(o[j][2], o[j][3]);
    }
    if (cq == 0) {
        g_m[sb + row_lo] = m_lo;  g_l[sb + row_lo] = l_lo;
        g_m[sb + row_hi] = m_hi;  g_l[sb + row_hi] = l_hi;
    }
}

// ---------------------------------------------------------------------------
// Combine split-KV partials.
// ---------------------------------------------------------------------------
__global__ __launch_bounds__(128)
void combine_kernel(float* __restrict__ out)
{
    const int tid = threadIdx.x;
    const int row = blockIdx.x * 8 + (tid >> 4);
    const int b   = blockIdx.y;
    const int c0  = (tid & 15) * 4;
    const int qi  = row >> 6;
    const int ns  = (qi + 1 < NS) ? (qi + 1) : NS;

    float m = -1e30f;
    #pragma unroll
    for (int s = 0; s < NS; s++)
        if (s < ns) m = fmaxf(m, g_m[(size_t)(b * NS + s) * SEQ + row]);

    float l = 0.f;
    float4 acc = make_float4(0.f, 0.f, 0.f, 0.f);
    #pragma unroll
    for (int s = 0; s < NS; s++) {
        if (s >= ns) break;
        size_t sb = (size_t)(b * NS + s) * SEQ + row;
        float wgt = __expf(g_m[sb] - m);
        l += g_l[sb] * wgt;
        float4 v = *(const float4*)(g_Om + sb * ADIM + c0);
        acc.x += v.x * wgt; acc.y += v.y * wgt;
        acc.z += v.z * wgt; acc.w += v.w * wgt;
    }
    float inv = 1.f / l;
    float4 r;
    r.x = rintf(acc.x * inv * 1e4f) * 1e-4f;
    r.y = rintf(acc.y * inv * 1e4f) * 1e-4f;
    r.z = rintf(acc.z * inv * 1e4f) * 1e-4f;
    r.w = rintf(acc.w * inv * 1e4f) * 1e-4f;
    *(float4*)(out + ((size_t)b * SEQ + row) * ADIM + c0) = r;
}

extern "C" void kernel_launch(void* const* d_in, const int* in_sizes, int n_in,
                              void* d_out, int out_size)
{
    const float* x  = (const float*)d_in[0];
    const float* wk = (const float*)d_in[1];
    const float* wq = (const float*)d_in[2];
    const float* wv = (const float*)d_in[3];
    float* out = (float*)d_out;

    cudaFuncSetAttribute(qkv_proj, cudaFuncAttributeMaxDynamicSharedMemorySize, QP_SMEM);
    qkv_proj<<<256, 256, QP_SMEM>>>(x, wk, wq, wv);

    cudaFuncSetAttribute(attn_kernel, cudaFuncAttributeMaxDynamicSharedMemorySize, SMEM_ATTN);
    attn_kernel<<<dim3((SEQ / 64) * NS, NB), 128, SMEM_ATTN>>>();

    combine_kernel<<<dim3(SEQ / 8, NB), 128>>>(out);
}

// round 16
// speedup vs baseline: 1.1577x; 1.0458x over previous
#include <cuda_runtime.h>
#include <cuda_fp16.h>
#include <math.h>

#define NB   4
#define SEQ  4096
#define EDIM 1024
#define ADIM 64
#define NS   8      // KV splits per q-tile

// Projected Q,K,V stored as split fp16 planes (hi + lo), [B*S, A] each.
// (V lo plane still written by projection; attention uses only Vh.)
__device__ __half g_Qh[NB * SEQ * ADIM];
__device__ __half g_Ql[NB * SEQ * ADIM];
__device__ __half g_Kh[NB * SEQ * ADIM];
__device__ __half g_Kl[NB * SEQ * ADIM];
__device__ __half g_Vh[NB * SEQ * ADIM];
__device__ __half g_Vl[NB * SEQ * ADIM];

// Split-KV partial results: O (unnormalized), row max m, row sum l.
__device__ float g_Om[NB * NS * SEQ * ADIM];   // 33.6 MB
__device__ float g_m [NB * NS * SEQ];
__device__ float g_l [NB * NS * SEQ];

// m16n8k16 f16 MMA, f32 accumulate, in-place C.
__device__ __forceinline__ void mma16816(float d[4], const unsigned a[4], const unsigned* b)
{
    asm volatile(
        "mma.sync.aligned.m16n8k16.row.col.f32.f16.f16.f32 "
        "{%0,%1,%2,%3}, {%4,%5,%6,%7}, {%8,%9}, {%0,%1,%2,%3};\n"
        : "+f"(d[0]), "+f"(d[1]), "+f"(d[2]), "+f"(d[3])
        : "r"(a[0]), "r"(a[1]), "r"(a[2]), "r"(a[3]), "r"(b[0]), "r"(b[1]));
}

// ldmatrix x4: 4 8x8 b16 matrices -> 4 regs/thread.
__device__ __forceinline__ void ldmx4(unsigned r[4], unsigned saddr)
{
    asm volatile(
        "ldmatrix.sync.aligned.m8n8.x4.shared.b16 {%0,%1,%2,%3}, [%4];\n"
        : "=r"(r[0]), "=r"(r[1]), "=r"(r[2]), "=r"(r[3]) : "r"(saddr));
}

// ldmatrix x4 transposed (for V^T fragments from row-major V).
__device__ __forceinline__ void ldmx4t(unsigned r[4], unsigned saddr)
{
    asm volatile(
        "ldmatrix.sync.aligned.m8n8.x4.trans.shared.b16 {%0,%1,%2,%3}, [%4];\n"
        : "=r"(r[0]), "=r"(r[1]), "=r"(r[2]), "=r"(r[3]) : "r"(saddr));
}

__device__ __forceinline__ void split1(float v, __half& h, __half& l)
{
    h = __float2half_rn(v);
    l = __float2half_rn(v - __half2float(h));
}

__device__ __forceinline__ void split2(float a, float b, unsigned& hi, unsigned& lo)
{
    __half2 h = __floats2half2_rn(a, b);
    float2 hf = __half22float2(h);
    __half2 l = __floats2half2_rn(a - hf.x, b - hf.y);
    hi = *(unsigned*)&h;
    lo = *(unsigned*)&l;
}

// Pack two floats into one fp16x2 word (hi plane only).
__device__ __forceinline__ unsigned pack2(float a, float b)
{
    __half2 h = __floats2half2_rn(a, b);
    return *(unsigned*)&h;
}

// 16-byte async copy global -> shared (cp.async.cg), generic dst.
__device__ __forceinline__ void cp16(void* smem_dst, const void* gsrc)
{
    unsigned sa = (unsigned)__cvta_generic_to_shared(smem_dst);
    asm volatile("cp.async.cg.shared.global [%0], [%1], 16;\n" :: "r"(sa), "l"(gsrc));
}

// 16-byte async copy global -> shared, u32 smem address.
__device__ __forceinline__ void cp16s(unsigned sa, const void* gsrc)
{
    asm volatile("cp.async.cg.shared.global [%0], [%1], 16;\n" :: "r"(sa), "l"(gsrc));
}

// ---------------------------------------------------------------------------
// QKV projection. X via cp.async double-buffer; W via direct LDG (L2-hot).
// Warp grid 2 rg x 4 cg (32 rows x 48 cols per warp). V columns (>=128)
// skip the X-lo MMA: V is consumed only as fp16 Vh, so sub-fp16 projection
// accuracy there is wasted work.
// Smem (bytes): Xraw[2][2048]f32 @0, Xh[64][40] @16384, Xl @21504,
//               Wh[192][40] @26624, Wl @41984; total 57344.
// ---------------------------------------------------------------------------
#define QP_SMEM 57344

__global__ __launch_bounds__(256, 2)
void qkv_proj(const float* __restrict__ x,
              const float* __restrict__ wk,
              const float* __restrict__ wq,
              const float* __restrict__ wv)
{
    extern __shared__ __align__(16) char qsm[];
    float*  Xraw = (float*)qsm;                    // [2][2048]
    __half* Xh   = (__half*)(qsm + 16384);         // [64][40]
    __half* Xl   = (__half*)(qsm + 21504);
    __half* Wh   = (__half*)(qsm + 26624);         // [192][40]
    __half* Wl   = (__half*)(qsm + 41984);

    const int tid  = threadIdx.x;
    const int warp = tid >> 5;
    const int lane = tid & 31;
    const int g    = lane >> 2;
    const int cq   = lane & 3;
    const int li   = lane & 7;
    const int lm   = lane >> 3;
    const int rg   = warp >> 2;          // row group 0..1 (32 rows)
    const int cg   = warp & 3;           // col group 0..3 (48 cols)
    const int rows0 = blockIdx.x * 64;

    const int xr  = tid >> 3;            // 0..31
    const int xc  = (tid & 7) * 4;
    const int wr0 = tid >> 3;            // W rows wr0 + 32k

    const unsigned aXh = (unsigned)__cvta_generic_to_shared(Xh)
                       + ((32 * rg + 8 * (lm & 1) + li) * 40 + 8 * (lm >> 1)) * 2;
    const unsigned aXl = aXh + 5120;
    const unsigned aWh = (unsigned)__cvta_generic_to_shared(Wh)
                       + ((cg * 48 + 8 * (lm >> 1) + li) * 40 + 8 * (lm & 1)) * 2;
    const unsigned aWl = aWh + 15360;

    // Per-thread W row sources (constant across iterations)
    const float* wsrc[6];
    #pragma unroll
    for (int k = 0; k < 6; k++) {
        int r = wr0 + 32 * k;
        wsrc[k] = (r < 64)  ? wk + (size_t)r * EDIM
                : (r < 128) ? wq + (size_t)(r - 64) * EDIM
                            : wv + (size_t)(r - 128) * EDIM;
    }

    float acc[2][6][4];
    #pragma unroll
    for (int m = 0; m < 2; m++)
        #pragma unroll
        for (int j = 0; j < 6; j++)
            #pragma unroll
            for (int i = 0; i < 4; i++) acc[m][j][i] = 0.f;

    cp16(Xraw + xr * 32 + xc,        x + (size_t)(rows0 + xr) * EDIM + xc);
    cp16(Xraw + (xr + 32) * 32 + xc, x + (size_t)(rows0 + xr + 32) * EDIM + xc);
    asm volatile("cp.async.commit_group;\n" ::: "memory");

    for (int it = 0; it < 32; it++) {
        const int buf = it & 1;
        const int e0  = it * 32;
        float* Xb = Xraw + buf * 2048;

        // W prefetch into registers (L2-hot)
        float4 wvreg[6];
        #pragma unroll
        for (int k = 0; k < 6; k++)
            wvreg[k] = *(const float4*)(wsrc[k] + e0 + xc);

        if (it + 1 < 32) {
            const int nbuf = (it + 1) & 1;
            const int e1   = (it + 1) * 32;
            float* Xn = Xraw + nbuf * 2048;
            cp16(Xn + xr * 32 + xc,        x + (size_t)(rows0 + xr) * EDIM + e1 + xc);
            cp16(Xn + (xr + 32) * 32 + xc, x + (size_t)(rows0 + xr + 32) * EDIM + e1 + xc);
            asm volatile("cp.async.commit_group;\n" ::: "memory");
            asm volatile("cp.async.wait_group 1;\n" ::: "memory");
        } else {
            asm volatile("cp.async.wait_group 0;\n" ::: "memory");
        }
        __syncthreads();   // prev MMA done with planes; X chunk `it` resident

        // split W registers -> planes
        #pragma unroll
        for (int k = 0; k < 6; k++) {
            int r = wr0 + 32 * k;
            __half h[4], l[4];
            split1(wvreg[k].x, h[0], l[0]); split1(wvreg[k].y, h[1], l[1]);
            split1(wvreg[k].z, h[2], l[2]); split1(wvreg[k].w, h[3], l[3]);
            *(uint2*)(Wh + r * 40 + xc) = *(uint2*)h;
            *(uint2*)(Wl + r * 40 + xc) = *(uint2*)l;
        }
        // split X raw -> planes
        #pragma unroll
        for (int k = 0; k < 2; k++) {
            int r = xr + 32 * k;
            float4 v = *(const float4*)(Xb + r * 32 + xc);
            __half h[4], l[4];
            split1(v.x, h[0], l[0]); split1(v.y, h[1], l[1]);
            split1(v.z, h[2], l[2]); split1(v.w, h[3], l[3]);
            *(uint2*)(Xh + r * 40 + xc) = *(uint2*)h;
            *(uint2*)(Xl + r * 40 + xc) = *(uint2*)l;
        }
        __syncthreads();

        // MMAs
        #pragma unroll
        for (int kc = 0; kc < 2; kc++) {
            unsigned ah[2][4], al[2][4];
            #pragma unroll
            for (int m = 0; m < 2; m++) {
                ldmx4(ah[m], aXh + m * 1280 + kc * 32);
                ldmx4(al[m], aXl + m * 1280 + kc * 32);
            }
            #pragma unroll
            for (int t = 0; t < 3; t++) {
                unsigned bh[4], bl[4];
                ldmx4(bh, aWh + t * 1280 + kc * 32);
                ldmx4(bl, aWl + t * 1280 + kc * 32);
                const bool needLo = (cg * 48 + 16 * t) < 128;  // warp-uniform
                #pragma unroll
                for (int m = 0; m < 2; m++) {
                    mma16816(acc[m][2 * t],     ah[m], bh);
                    mma16816(acc[m][2 * t],     ah[m], bl);
                    mma16816(acc[m][2 * t + 1], ah[m], bh + 2);
                    mma16816(acc[m][2 * t + 1], ah[m], bl + 2);
                    if (needLo) {
                        mma16816(acc[m][2 * t],     al[m], bh);
                        mma16816(acc[m][2 * t + 1], al[m], bh + 2);
                    }
                }
            }
        }
    }

    #pragma unroll
    for (int m = 0; m < 2; m++) {
        const int row_lo = rows0 + 32 * rg + 16 * m + g;
        const int row_hi = row_lo + 8;
        #pragma unroll
        for (int j = 0; j < 6; j++) {
            int colg = cg * 48 + 8 * j + 2 * cq;
            __half *dh, *dl;
            float sc = 1.f;
            int cl;
            if (colg < 64)       { dh = g_Kh; dl = g_Kl; cl = colg; }
            else if (colg < 128) { dh = g_Qh; dl = g_Ql; cl = colg - 64; sc = 0.125f; }
            else                 { dh = g_Vh; dl = g_Vl; cl = colg - 128; }

            unsigned h2, l2;
            split2(acc[m][j][0] * sc, acc[m][j][1] * sc, h2, l2);
            *(unsigned*)(dh + (size_t)row_lo * ADIM + cl) = h2;
            *(unsigned*)(dl + (size_t)row_lo * ADIM + cl) = l2;
            split2(acc[m][j][2] * sc, acc[m][j][3] * sc, h2, l2);
            *(unsigned*)(dh + (size_t)row_hi * ADIM + cl) = h2;
            *(unsigned*)(dl + (size_t)row_hi * ADIM + cl) = l2;
        }
    }
}

// ---------------------------------------------------------------------------
// Causal flash attention, split-KV (NS=8), 64-row q-tile, cp.async double-
// buffered K/V tiles. K hi/lo split; V and P single fp16 plane
// (PV = Ph*Vh — the Pl and Vl terms are each ~2^-11 of the result, matching
// fp16 rounding already present).
// Stage = Kh[64][72] + Kl + Vh = 13824 halves (27648 B); 2 stages = 55296 B.
// ---------------------------------------------------------------------------
#define ST 72
#define OFF_KH 0
#define OFF_KL 4608
#define OFF_VH 9216
#define STAGE_BYTES  27648
#define SMEM_ATTN    (2 * STAGE_BYTES)

__global__ __launch_bounds__(128, 4)
void attn_kernel()
{
    extern __shared__ __align__(16) __half sh[];

    const int tid  = threadIdx.x;
    const int w    = tid >> 5;
    const int lane = tid & 31;
    const int g    = lane >> 2;
    const int cq   = lane & 3;
    const int li   = lane & 7;
    const int lm   = lane >> 3;
    const int bx   = blockIdx.x;
    const int s    = bx & (NS - 1);
    const int qi   = (SEQ / 64 - 1) - (bx >> 3);
    const int b    = blockIdx.y;
    const int q0   = qi * 64;

    if (qi < s) return;

    const unsigned shu = (unsigned)__cvta_generic_to_shared(sh);
    const unsigned lrowK = ((8 * (lm >> 1) + li) * ST + 8 * (lm & 1)) * 2;
    const unsigned lrowV = ((8 * (lm & 1) + li) * ST + 8 * (lm >> 1)) * 2;

    unsigned qh[4][4], ql[4][4];
    {
        size_t rl = (size_t)(b * SEQ + q0 + 16 * w + g) * ADIM;
        size_t rh = rl + 8 * ADIM;
        #pragma unroll
        for (int kc = 0; kc < 4; kc++) {
            int off = 16 * kc + 2 * cq;
            qh[kc][0] = *(const unsigned*)(g_Qh + rl + off);
            qh[kc][1] = *(const unsigned*)(g_Qh + rh + off);
            qh[kc][2] = *(const unsigned*)(g_Qh + rl + off + 8);
            qh[kc][3] = *(const unsigned*)(g_Qh + rh + off + 8);
            ql[kc][0] = *(const unsigned*)(g_Ql + rl + off);
            ql[kc][1] = *(const unsigned*)(g_Ql + rh + off);
            ql[kc][2] = *(const unsigned*)(g_Ql + rl + off + 8);
            ql[kc][3] = *(const unsigned*)(g_Ql + rh + off + 8);
        }
    }

    float o[8][4];
    #pragma unroll
    for (int j = 0; j < 8; j++)
        #pragma unroll
        for (int i = 0; i < 4; i++) o[j][i] = 0.f;
    float m_lo = -1e30f, m_hi = -1e30f, l_lo = 0.f, l_hi = 0.f;

    // ---- issue tile kb=s into stage 0
    {
        const __half* sKh = g_Kh + (size_t)(b * SEQ + s * 64) * ADIM;
        const __half* sKl = g_Kl + (size_t)(b * SEQ + s * 64) * ADIM;
        const __half* sVh = g_Vh + (size_t)(b * SEQ + s * 64) * ADIM;
        #pragma unroll
        for (int k = 0; k < 4; k++) {
            int f = tid + 128 * k;
            int r = f >> 3, c = f & 7;
            unsigned d = shu + (r * ST + 8 * c) * 2;
            const size_t gsrc = (size_t)r * ADIM + 8 * c;
            cp16s(d + OFF_KH * 2, sKh + gsrc);
            cp16s(d + OFF_KL * 2, sKl + gsrc);
            cp16s(d + OFF_VH * 2, sVh + gsrc);
        }
        asm volatile("cp.async.commit_group;\n" ::: "memory");
    }

    int stg = 0;
    for (int kb = s; kb <= qi; kb += NS) {
        if (kb + NS <= qi) {
            const unsigned sb2 = shu + (stg ^ 1) * STAGE_BYTES;
            const __half* sKh = g_Kh + (size_t)(b * SEQ + (kb + NS) * 64) * ADIM;
            const __half* sKl = g_Kl + (size_t)(b * SEQ + (kb + NS) * 64) * ADIM;
            const __half* sVh = g_Vh + (size_t)(b * SEQ + (kb + NS) * 64) * ADIM;
            #pragma unroll
            for (int k = 0; k < 4; k++) {
                int f = tid + 128 * k;
                int r = f >> 3, c = f & 7;
                unsigned d = sb2 + (r * ST + 8 * c) * 2;
                const size_t gsrc = (size_t)r * ADIM + 8 * c;
                cp16s(d + OFF_KH * 2, sKh + gsrc);
                cp16s(d + OFF_KL * 2, sKl + gsrc);
                cp16s(d + OFF_VH * 2, sVh + gsrc);
            }
            asm volatile("cp.async.commit_group;\n" ::: "memory");
            asm volatile("cp.async.wait_group 1;\n" ::: "memory");
        } else {
            asm volatile("cp.async.wait_group 0;\n" ::: "memory");
        }
        __syncthreads();   // current stage resident for all warps

        const unsigned sb = shu + stg * STAGE_BYTES;
        const unsigned aKh = sb + OFF_KH * 2 + lrowK;
        const unsigned aKl = sb + OFF_KL * 2 + lrowK;
        const unsigned aVh = sb + OFF_VH * 2 + lrowV;

        // ---- S = Q K^T
        float sreg[8][4];
        #pragma unroll
        for (int j = 0; j < 8; j++)
            #pragma unroll
            for (int i = 0; i < 4; i++) sreg[j][i] = 0.f;

        #pragma unroll
        for (int kc = 0; kc < 4; kc++) {
            #pragma unroll
            for (int t = 0; t < 4; t++) {
                unsigned bh[4], bl[4];
                ldmx4(bh, aKh + t * 2304 + kc * 32);
                ldmx4(bl, aKl + t * 2304 + kc * 32);
                mma16816(sreg[2 * t],     qh[kc], bh);
                mma16816(sreg[2 * t],     qh[kc], bl);
                mma16816(sreg[2 * t],     ql[kc], bh);
                mma16816(sreg[2 * t + 1], qh[kc], bh + 2);
                mma16816(sreg[2 * t + 1], qh[kc], bl + 2);
                mma16816(sreg[2 * t + 1], ql[kc], bh + 2);
            }
        }

        if (kb == qi) {
            int r_lo = 16 * w + g, r_hi = r_lo + 8;
            #pragma unroll
            for (int j = 0; j < 8; j++) {
                int c0 = 8 * j + 2 * cq;
                if (c0     > r_lo) sreg[j][0] = -1e30f;
                if (c0 + 1 > r_lo) sreg[j][1] = -1e30f;
                if (c0     > r_hi) sreg[j][2] = -1e30f;
                if (c0 + 1 > r_hi) sreg[j][3] = -1e30f;
            }
        }

        // ---- online softmax
        float mx0 = -1e30f, mx1 = -1e30f;
        #pragma unroll
        for (int j = 0; j < 8; j++) {
            mx0 = fmaxf(mx0, fmaxf(sreg[j][0], sreg[j][1]));
            mx1 = fmaxf(mx1, fmaxf(sreg[j][2], sreg[j][3]));
        }
        mx0 = fmaxf(mx0, __shfl_xor_sync(0xffffffffu, mx0, 1));
        mx0 = fmaxf(mx0, __shfl_xor_sync(0xffffffffu, mx0, 2));
        mx1 = fmaxf(mx1, __shfl_xor_sync(0xffffffffu, mx1, 1));
        mx1 = fmaxf(mx1, __shfl_xor_sync(0xffffffffu, mx1, 2));
        float mn0 = fmaxf(m_lo, mx0), mn1 = fmaxf(m_hi, mx1);
        float sc0 = __expf(m_lo - mn0), sc1 = __expf(m_hi - mn1);
        m_lo = mn0; m_hi = mn1;
        float su0 = 0.f, su1 = 0.f;
        #pragma unroll
        for (int j = 0; j < 8; j++) {
            sreg[j][0] = __expf(sreg[j][0] - mn0);
            sreg[j][1] = __expf(sreg[j][1] - mn0);
            sreg[j][2] = __expf(sreg[j][2] - mn1);
            sreg[j][3] = __expf(sreg[j][3] - mn1);
            su0 += sreg[j][0] + sreg[j][1];
            su1 += sreg[j][2] + sreg[j][3];
        }
        su0 += __shfl_xor_sync(0xffffffffu, su0, 1);
        su0 += __shfl_xor_sync(0xffffffffu, su0, 2);
        su1 += __shfl_xor_sync(0xffffffffu, su1, 1);
        su1 += __shfl_xor_sync(0xffffffffu, su1, 2);
        l_lo = l_lo * sc0 + su0;
        l_hi = l_hi * sc1 + su1;
        #pragma unroll
        for (int j = 0; j < 8; j++) {
            o[j][0] *= sc0; o[j][1] *= sc0;
            o[j][2] *= sc1; o[j][3] *= sc1;
        }

        // ---- O += P V (P single fp16 plane, V single plane)
        #pragma unroll
        for (int kc = 0; kc < 4; kc++) {
            unsigned ph[4];
            ph[0] = pack2(sreg[2 * kc][0],     sreg[2 * kc][1]);
            ph[1] = pack2(sreg[2 * kc][2],     sreg[2 * kc][3]);
            ph[2] = pack2(sreg[2 * kc + 1][0], sreg[2 * kc + 1][1]);
            ph[3] = pack2(sreg[2 * kc + 1][2], sreg[2 * kc + 1][3]);
            #pragma unroll
            for (int t = 0; t < 4; t++) {
                unsigned bh[4];
                ldmx4t(bh, aVh + kc * 2304 + t * 32);
                mma16816(o[2 * t],     ph, bh);
                mma16816(o[2 * t + 1], ph, bh + 2);
            }
        }

        __syncthreads();   // all warps done with stage `stg` before reuse
        stg ^= 1;
    }

    const int row_lo = q0 + 16 * w + g;
    const int row_hi = row_lo + 8;
    const size_t sb  = (size_t)(b * NS + s) * SEQ;
    #pragma unroll
    for (int j = 0; j < 8; j++) {
        int col = 8 * j + 2 * cq;
        *(float2*)(g_Om + (sb + row_lo) * ADIM + col) = make_float2(o[j][0], o[j][1]);
        *(float2*)(g_Om + (sb + row_hi) * ADIM + col) = make_float2(o[j][2], o[j][3]);
    }
    if (cq == 0) {
        g_m[sb + row_lo] = m_lo;  g_l[sb + row_lo] = l_lo;
        g_m[sb + row_hi] = m_hi;  g_l[sb + row_hi] = l_hi;
    }
}

// ---------------------------------------------------------------------------
// Combine split-KV partials.
// ---------------------------------------------------------------------------
__global__ __launch_bounds__(128)
void combine_kernel(float* __restrict__ out)
{
    const int tid = threadIdx.x;
    const int row = blockIdx.x * 8 + (tid >> 4);
    const int b   = blockIdx.y;
    const int c0  = (tid & 15) * 4;
    const int qi  = row >> 6;
    const int ns  = (qi + 1 < NS) ? (qi + 1) : NS;

    float m = -1e30f;
    #pragma unroll
    for (int s = 0; s < NS; s++)
        if (s < ns) m = fmaxf(m, g_m[(size_t)(b * NS + s) * SEQ + row]);

    float l = 0.f;
    float4 acc = make_float4(0.f, 0.f, 0.f, 0.f);
    #pragma unroll
    for (int s = 0; s < NS; s++) {
        if (s >= ns) break;
        size_t sb = (size_t)(b * NS + s) * SEQ + row;
        float wgt = __expf(g_m[sb] - m);
        l += g_l[sb] * wgt;
        float4 v = *(const float4*)(g_Om + sb * ADIM + c0);
        acc.x += v.x * wgt; acc.y += v.y * wgt;
        acc.z += v.z * wgt; acc.w += v.w * wgt;
    }
    float inv = 1.f / l;
    float4 r;
    r.x = rintf(acc.x * inv * 1e4f) * 1e-4f;
    r.y = rintf(acc.y * inv * 1e4f) * 1e-4f;
    r.z = rintf(acc.z * inv * 1e4f) * 1e-4f;
    r.w = rintf(acc.w * inv * 1e4f) * 1e-4f;
    *(float4*)(out + ((size_t)b * SEQ + row) * ADIM + c0) = r;
}

extern "C" void kernel_launch(void* const* d_in, const int* in_sizes, int n_in,
                              void* d_out, int out_size)
{
    const float* x  = (const float*)d_in[0];
    const float* wk = (const float*)d_in[1];
    const float* wq = (const float*)d_in[2];
    const float* wv = (const float*)d_in[3];
    float* out = (float*)d_out;

    cudaFuncSetAttribute(qkv_proj, cudaFuncAttributeMaxDynamicSharedMemorySize, QP_SMEM);
    qkv_proj<<<256, 256, QP_SMEM>>>(x, wk, wq, wv);

    cudaFuncSetAttribute(attn_kernel, cudaFuncAttributeMaxDynamicSharedMemorySize, SMEM_ATTN);
    attn_kernel<<<dim3((SEQ / 64) * NS, NB), 128, SMEM_ATTN>>>();

    combine_kernel<<<dim3(SEQ / 8, NB), 128>>>(out);
}

// round 17
// speedup vs baseline: 1.2103x; 1.0454x over previous
#include <cuda_runtime.h>
#include <cuda_fp16.h>
#include <math.h>

#define NB   4
#define SEQ  4096
#define EDIM 1024
#define ADIM 64
#define NS   8      // KV splits per q-tile

// Projected Q,K stored as split fp16 planes (hi + lo); V hi plane only
// (V-lo is never consumed by attention since R11).
__device__ __half g_Qh[NB * SEQ * ADIM];
__device__ __half g_Ql[NB * SEQ * ADIM];
__device__ __half g_Kh[NB * SEQ * ADIM];
__device__ __half g_Kl[NB * SEQ * ADIM];
__device__ __half g_Vh[NB * SEQ * ADIM];

// Split-KV partial results: O (unnormalized), row max m, row sum l.
__device__ float g_Om[NB * NS * SEQ * ADIM];   // 33.6 MB
__device__ float g_m [NB * NS * SEQ];
__device__ float g_l [NB * NS * SEQ];

// m16n8k16 f16 MMA, f32 accumulate, in-place C.
__device__ __forceinline__ void mma16816(float d[4], const unsigned a[4], const unsigned* b)
{
    asm volatile(
        "mma.sync.aligned.m16n8k16.row.col.f32.f16.f16.f32 "
        "{%0,%1,%2,%3}, {%4,%5,%6,%7}, {%8,%9}, {%0,%1,%2,%3};\n"
        : "+f"(d[0]), "+f"(d[1]), "+f"(d[2]), "+f"(d[3])
        : "r"(a[0]), "r"(a[1]), "r"(a[2]), "r"(a[3]), "r"(b[0]), "r"(b[1]));
}

// ldmatrix x4: 4 8x8 b16 matrices -> 4 regs/thread.
__device__ __forceinline__ void ldmx4(unsigned r[4], unsigned saddr)
{
    asm volatile(
        "ldmatrix.sync.aligned.m8n8.x4.shared.b16 {%0,%1,%2,%3}, [%4];\n"
        : "=r"(r[0]), "=r"(r[1]), "=r"(r[2]), "=r"(r[3]) : "r"(saddr));
}

// ldmatrix x4 transposed (for V^T fragments from row-major V).
__device__ __forceinline__ void ldmx4t(unsigned r[4], unsigned saddr)
{
    asm volatile(
        "ldmatrix.sync.aligned.m8n8.x4.trans.shared.b16 {%0,%1,%2,%3}, [%4];\n"
        : "=r"(r[0]), "=r"(r[1]), "=r"(r[2]), "=r"(r[3]) : "r"(saddr));
}

__device__ __forceinline__ void split1(float v, __half& h, __half& l)
{
    h = __float2half_rn(v);
    l = __float2half_rn(v - __half2float(h));
}

__device__ __forceinline__ void split2(float a, float b, unsigned& hi, unsigned& lo)
{
    __half2 h = __floats2half2_rn(a, b);
    float2 hf = __half22float2(h);
    __half2 l = __floats2half2_rn(a - hf.x, b - hf.y);
    hi = *(unsigned*)&h;
    lo = *(unsigned*)&l;
}

// Pack two floats into one fp16x2 word (hi plane only).
__device__ __forceinline__ unsigned pack2(float a, float b)
{
    __half2 h = __floats2half2_rn(a, b);
    return *(unsigned*)&h;
}

// 16-byte async copy global -> shared (cp.async.cg), generic dst.
__device__ __forceinline__ void cp16(void* smem_dst, const void* gsrc)
{
    unsigned sa = (unsigned)__cvta_generic_to_shared(smem_dst);
    asm volatile("cp.async.cg.shared.global [%0], [%1], 16;\n" :: "r"(sa), "l"(gsrc));
}

// 16-byte async copy global -> shared, u32 smem address.
__device__ __forceinline__ void cp16s(unsigned sa, const void* gsrc)
{
    asm volatile("cp.async.cg.shared.global [%0], [%1], 16;\n" :: "r"(sa), "l"(gsrc));
}

// ---------------------------------------------------------------------------
// QKV projection — uniform MMA block (R12 version, measured 65.6-66.2us).
// X via cp.async double-buffer; W via direct LDG (L2-hot) + inline split.
// Warp grid 2 rg x 4 cg. Epilogue: V stores hi plane only (lo is dead).
// Smem (bytes): Xraw[2][2048]f32 @0, Xh[64][40] @16384, Xl @21504,
//               Wh[192][40] @26624, Wl @41984; total 57344.
// ---------------------------------------------------------------------------
#define QP_SMEM 57344

__global__ __launch_bounds__(256, 2)
void qkv_proj(const float* __restrict__ x,
              const float* __restrict__ wk,
              const float* __restrict__ wq,
              const float* __restrict__ wv)
{
    extern __shared__ __align__(16) char qsm[];
    float*  Xraw = (float*)qsm;                    // [2][2048]
    __half* Xh   = (__half*)(qsm + 16384);         // [64][40]
    __half* Xl   = (__half*)(qsm + 21504);
    __half* Wh   = (__half*)(qsm + 26624);         // [192][40]
    __half* Wl   = (__half*)(qsm + 41984);

    const int tid  = threadIdx.x;
    const int warp = tid >> 5;
    const int lane = tid & 31;
    const int g    = lane >> 2;
    const int cq   = lane & 3;
    const int li   = lane & 7;
    const int lm   = lane >> 3;
    const int rg   = warp >> 2;          // row group 0..1 (32 rows)
    const int cg   = warp & 3;           // col group 0..3 (48 cols)
    const int rows0 = blockIdx.x * 64;

    const int xr  = tid >> 3;            // 0..31
    const int xc  = (tid & 7) * 4;
    const int wr0 = tid >> 3;            // W rows wr0 + 32k

    const unsigned aXh = (unsigned)__cvta_generic_to_shared(Xh)
                       + ((32 * rg + 8 * (lm & 1) + li) * 40 + 8 * (lm >> 1)) * 2;
    const unsigned aXl = aXh + 5120;
    const unsigned aWh = (unsigned)__cvta_generic_to_shared(Wh)
                       + ((cg * 48 + 8 * (lm >> 1) + li) * 40 + 8 * (lm & 1)) * 2;
    const unsigned aWl = aWh + 15360;

    // Per-thread W row sources (constant across iterations)
    const float* wsrc[6];
    #pragma unroll
    for (int k = 0; k < 6; k++) {
        int r = wr0 + 32 * k;
        wsrc[k] = (r < 64)  ? wk + (size_t)r * EDIM
                : (r < 128) ? wq + (size_t)(r - 64) * EDIM
                            : wv + (size_t)(r - 128) * EDIM;
    }

    float acc[2][6][4];
    #pragma unroll
    for (int m = 0; m < 2; m++)
        #pragma unroll
        for (int j = 0; j < 6; j++)
            #pragma unroll
            for (int i = 0; i < 4; i++) acc[m][j][i] = 0.f;

    cp16(Xraw + xr * 32 + xc,        x + (size_t)(rows0 + xr) * EDIM + xc);
    cp16(Xraw + (xr + 32) * 32 + xc, x + (size_t)(rows0 + xr + 32) * EDIM + xc);
    asm volatile("cp.async.commit_group;\n" ::: "memory");

    for (int it = 0; it < 32; it++) {
        const int buf = it & 1;
        const int e0  = it * 32;
        float* Xb = Xraw + buf * 2048;

        // W prefetch into registers (L2-hot)
        float4 wvreg[6];
        #pragma unroll
        for (int k = 0; k < 6; k++)
            wvreg[k] = *(const float4*)(wsrc[k] + e0 + xc);

        if (it + 1 < 32) {
            const int nbuf = (it + 1) & 1;
            const int e1   = (it + 1) * 32;
            float* Xn = Xraw + nbuf * 2048;
            cp16(Xn + xr * 32 + xc,        x + (size_t)(rows0 + xr) * EDIM + e1 + xc);
            cp16(Xn + (xr + 32) * 32 + xc, x + (size_t)(rows0 + xr + 32) * EDIM + e1 + xc);
            asm volatile("cp.async.commit_group;\n" ::: "memory");
            asm volatile("cp.async.wait_group 1;\n" ::: "memory");
        } else {
            asm volatile("cp.async.wait_group 0;\n" ::: "memory");
        }
        __syncthreads();   // prev MMA done with planes; X chunk `it` resident

        // split W registers -> planes
        #pragma unroll
        for (int k = 0; k < 6; k++) {
            int r = wr0 + 32 * k;
            __half h[4], l[4];
            split1(wvreg[k].x, h[0], l[0]); split1(wvreg[k].y, h[1], l[1]);
            split1(wvreg[k].z, h[2], l[2]); split1(wvreg[k].w, h[3], l[3]);
            *(uint2*)(Wh + r * 40 + xc) = *(uint2*)h;
            *(uint2*)(Wl + r * 40 + xc) = *(uint2*)l;
        }
        // split X raw -> planes
        #pragma unroll
        for (int k = 0; k < 2; k++) {
            int r = xr + 32 * k;
            float4 v = *(const float4*)(Xb + r * 32 + xc);
            __half h[4], l[4];
            split1(v.x, h[0], l[0]); split1(v.y, h[1], l[1]);
            split1(v.z, h[2], l[2]); split1(v.w, h[3], l[3]);
            *(uint2*)(Xh + r * 40 + xc) = *(uint2*)h;
            *(uint2*)(Xl + r * 40 + xc) = *(uint2*)l;
        }
        __syncthreads();

        // MMAs (uniform — no conditional skipping)
        #pragma unroll
        for (int kc = 0; kc < 2; kc++) {
            unsigned ah[2][4], al[2][4];
            #pragma unroll
            for (int m = 0; m < 2; m++) {
                ldmx4(ah[m], aXh + m * 1280 + kc * 32);
                ldmx4(al[m], aXl + m * 1280 + kc * 32);
            }
            #pragma unroll
            for (int t = 0; t < 3; t++) {
                unsigned bh[4], bl[4];
                ldmx4(bh, aWh + t * 1280 + kc * 32);
                ldmx4(bl, aWl + t * 1280 + kc * 32);
                #pragma unroll
                for (int m = 0; m < 2; m++) {
                    mma16816(acc[m][2 * t],     ah[m], bh);
                    mma16816(acc[m][2 * t],     ah[m], bl);
                    mma16816(acc[m][2 * t],     al[m], bh);
                    mma16816(acc[m][2 * t + 1], ah[m], bh + 2);
                    mma16816(acc[m][2 * t + 1], ah[m], bl + 2);
                    mma16816(acc[m][2 * t + 1], al[m], bh + 2);
                }
            }
        }
    }

    #pragma unroll
    for (int m = 0; m < 2; m++) {
        const int row_lo = rows0 + 32 * rg + 16 * m + g;
        const int row_hi = row_lo + 8;
        #pragma unroll
        for (int j = 0; j < 6; j++) {
            int colg = cg * 48 + 8 * j + 2 * cq;
            if (colg < 64) {           // K: hi + lo planes
                int cl = colg;
                unsigned h2, l2;
                split2(acc[m][j][0], acc[m][j][1], h2, l2);
                *(unsigned*)(g_Kh + (size_t)row_lo * ADIM + cl) = h2;
                *(unsigned*)(g_Kl + (size_t)row_lo * ADIM + cl) = l2;
                split2(acc[m][j][2], acc[m][j][3], h2, l2);
                *(unsigned*)(g_Kh + (size_t)row_hi * ADIM + cl) = h2;
                *(unsigned*)(g_Kl + (size_t)row_hi * ADIM + cl) = l2;
            } else if (colg < 128) {   // Q: scaled, hi + lo planes
                int cl = colg - 64;
                unsigned h2, l2;
                split2(acc[m][j][0] * 0.125f, acc[m][j][1] * 0.125f, h2, l2);
                *(unsigned*)(g_Qh + (size_t)row_lo * ADIM + cl) = h2;
                *(unsigned*)(g_Ql + (size_t)row_lo * ADIM + cl) = l2;
                split2(acc[m][j][2] * 0.125f, acc[m][j][3] * 0.125f, h2, l2);
                *(unsigned*)(g_Qh + (size_t)row_hi * ADIM + cl) = h2;
                *(unsigned*)(g_Ql + (size_t)row_hi * ADIM + cl) = l2;
            } else {                   // V: hi plane only (lo is dead)
                int cl = colg - 128;
                *(unsigned*)(g_Vh + (size_t)row_lo * ADIM + cl) =
                    pack2(acc[m][j][0], acc[m][j][1]);
                *(unsigned*)(g_Vh + (size_t)row_hi * ADIM + cl) =
                    pack2(acc[m][j][2], acc[m][j][3]);
            }
        }
    }
}

// ---------------------------------------------------------------------------
// Causal flash attention, split-KV (NS=8), 64-row q-tile, cp.async double-
// buffered K/V tiles. K hi/lo split; V and P single fp16 plane.
// Stage = Kh[64][72] + Kl + Vh = 13824 halves (27648 B); 2 stages = 55296 B.
// Unchanged from R15 (the winner).
// ---------------------------------------------------------------------------
#define ST 72
#define OFF_KH 0
#define OFF_KL 4608
#define OFF_VH 9216
#define STAGE_BYTES  27648
#define SMEM_ATTN    (2 * STAGE_BYTES)

__global__ __launch_bounds__(128, 4)
void attn_kernel()
{
    extern __shared__ __align__(16) __half sh[];

    const int tid  = threadIdx.x;
    const int w    = tid >> 5;
    const int lane = tid & 31;
    const int g    = lane >> 2;
    const int cq   = lane & 3;
    const int li   = lane & 7;
    const int lm   = lane >> 3;
    const int bx   = blockIdx.x;
    const int s    = bx & (NS - 1);
    const int qi   = (SEQ / 64 - 1) - (bx >> 3);
    const int b    = blockIdx.y;
    const int q0   = qi * 64;

    if (qi < s) return;

    const unsigned shu = (unsigned)__cvta_generic_to_shared(sh);
    const unsigned lrowK = ((8 * (lm >> 1) + li) * ST + 8 * (lm & 1)) * 2;
    const unsigned lrowV = ((8 * (lm & 1) + li) * ST + 8 * (lm >> 1)) * 2;

    unsigned qh[4][4], ql[4][4];
    {
        size_t rl = (size_t)(b * SEQ + q0 + 16 * w + g) * ADIM;
        size_t rh = rl + 8 * ADIM;
        #pragma unroll
        for (int kc = 0; kc < 4; kc++) {
            int off = 16 * kc + 2 * cq;
            qh[kc][0] = *(const unsigned*)(g_Qh + rl + off);
            qh[kc][1] = *(const unsigned*)(g_Qh + rh + off);
            qh[kc][2] = *(const unsigned*)(g_Qh + rl + off + 8);
            qh[kc][3] = *(const unsigned*)(g_Qh + rh + off + 8);
            ql[kc][0] = *(const unsigned*)(g_Ql + rl + off);
            ql[kc][1] = *(const unsigned*)(g_Ql + rh + off);
            ql[kc][2] = *(const unsigned*)(g_Ql + rl + off + 8);
            ql[kc][3] = *(const unsigned*)(g_Ql + rh + off + 8);
        }
    }

    float o[8][4];
    #pragma unroll
    for (int j = 0; j < 8; j++)
        #pragma unroll
        for (int i = 0; i < 4; i++) o[j][i] = 0.f;
    float m_lo = -1e30f, m_hi = -1e30f, l_lo = 0.f, l_hi = 0.f;

    // ---- issue tile kb=s into stage 0
    {
        const __half* sKh = g_Kh + (size_t)(b * SEQ + s * 64) * ADIM;
        const __half* sKl = g_Kl + (size_t)(b * SEQ + s * 64) * ADIM;
        const __half* sVh = g_Vh + (size_t)(b * SEQ + s * 64) * ADIM;
        #pragma unroll
        for (int k = 0; k < 4; k++) {
            int f = tid + 128 * k;
            int r = f >> 3, c = f & 7;
            unsigned d = shu + (r * ST + 8 * c) * 2;
            const size_t gsrc = (size_t)r * ADIM + 8 * c;
            cp16s(d + OFF_KH * 2, sKh + gsrc);
            cp16s(d + OFF_KL * 2, sKl + gsrc);
            cp16s(d + OFF_VH * 2, sVh + gsrc);
        }
        asm volatile("cp.async.commit_group;\n" ::: "memory");
    }

    int stg = 0;
    for (int kb = s; kb <= qi; kb += NS) {
        if (kb + NS <= qi) {
            const unsigned sb2 = shu + (stg ^ 1) * STAGE_BYTES;
            const __half* sKh = g_Kh + (size_t)(b * SEQ + (kb + NS) * 64) * ADIM;
            const __half* sKl = g_Kl + (size_t)(b * SEQ + (kb + NS) * 64) * ADIM;
            const __half* sVh = g_Vh + (size_t)(b * SEQ + (kb + NS) * 64) * ADIM;
            #pragma unroll
            for (int k = 0; k < 4; k++) {
                int f = tid + 128 * k;
                int r = f >> 3, c = f & 7;
                unsigned d = sb2 + (r * ST + 8 * c) * 2;
                const size_t gsrc = (size_t)r * ADIM + 8 * c;
                cp16s(d + OFF_KH * 2, sKh + gsrc);
                cp16s(d + OFF_KL * 2, sKl + gsrc);
                cp16s(d + OFF_VH * 2, sVh + gsrc);
            }
            asm volatile("cp.async.commit_group;\n" ::: "memory");
            asm volatile("cp.async.wait_group 1;\n" ::: "memory");
        } else {
            asm volatile("cp.async.wait_group 0;\n" ::: "memory");
        }
        __syncthreads();   // current stage resident for all warps

        const unsigned sb = shu + stg * STAGE_BYTES;
        const unsigned aKh = sb + OFF_KH * 2 + lrowK;
        const unsigned aKl = sb + OFF_KL * 2 + lrowK;
        const unsigned aVh = sb + OFF_VH * 2 + lrowV;

        // ---- S = Q K^T
        float sreg[8][4];
        #pragma unroll
        for (int j = 0; j < 8; j++)
            #pragma unroll
            for (int i = 0; i < 4; i++) sreg[j][i] = 0.f;

        #pragma unroll
        for (int kc = 0; kc < 4; kc++) {
            #pragma unroll
            for (int t = 0; t < 4; t++) {
                unsigned bh[4], bl[4];
                ldmx4(bh, aKh + t * 2304 + kc * 32);
                ldmx4(bl, aKl + t * 2304 + kc * 32);
                mma16816(sreg[2 * t],     qh[kc], bh);
                mma16816(sreg[2 * t],     qh[kc], bl);
                mma16816(sreg[2 * t],     ql[kc], bh);
                mma16816(sreg[2 * t + 1], qh[kc], bh + 2);
                mma16816(sreg[2 * t + 1], qh[kc], bl + 2);
                mma16816(sreg[2 * t + 1], ql[kc], bh + 2);
            }
        }

        if (kb == qi) {
            int r_lo = 16 * w + g, r_hi = r_lo + 8;
            #pragma unroll
            for (int j = 0; j < 8; j++) {
                int c0 = 8 * j + 2 * cq;
                if (c0     > r_lo) sreg[j][0] = -1e30f;
                if (c0 + 1 > r_lo) sreg[j][1] = -1e30f;
                if (c0     > r_hi) sreg[j][2] = -1e30f;
                if (c0 + 1 > r_hi) sreg[j][3] = -1e30f;
            }
        }

        // ---- online softmax
        float mx0 = -1e30f, mx1 = -1e30f;
        #pragma unroll
        for (int j = 0; j < 8; j++) {
            mx0 = fmaxf(mx0, fmaxf(sreg[j][0], sreg[j][1]));
            mx1 = fmaxf(mx1, fmaxf(sreg[j][2], sreg[j][3]));
        }
        mx0 = fmaxf(mx0, __shfl_xor_sync(0xffffffffu, mx0, 1));
        mx0 = fmaxf(mx0, __shfl_xor_sync(0xffffffffu, mx0, 2));
        mx1 = fmaxf(mx1, __shfl_xor_sync(0xffffffffu, mx1, 1));
        mx1 = fmaxf(mx1, __shfl_xor_sync(0xffffffffu, mx1, 2));
        float mn0 = fmaxf(m_lo, mx0), mn1 = fmaxf(m_hi, mx1);
        float sc0 = __expf(m_lo - mn0), sc1 = __expf(m_hi - mn1);
        m_lo = mn0; m_hi = mn1;
        float su0 = 0.f, su1 = 0.f;
        #pragma unroll
        for (int j = 0; j < 8; j++) {
            sreg[j][0] = __expf(sreg[j][0] - mn0);
            sreg[j][1] = __expf(sreg[j][1] - mn0);
            sreg[j][2] = __expf(sreg[j][2] - mn1);
            sreg[j][3] = __expf(sreg[j][3] - mn1);
            su0 += sreg[j][0] + sreg[j][1];
            su1 += sreg[j][2] + sreg[j][3];
        }
        su0 += __shfl_xor_sync(0xffffffffu, su0, 1);
        su0 += __shfl_xor_sync(0xffffffffu, su0, 2);
        su1 += __shfl_xor_sync(0xffffffffu, su1, 1);
        su1 += __shfl_xor_sync(0xffffffffu, su1, 2);
        l_lo = l_lo * sc0 + su0;
        l_hi = l_hi * sc1 + su1;
        #pragma unroll
        for (int j = 0; j < 8; j++) {
            o[j][0] *= sc0; o[j][1] *= sc0;
            o[j][2] *= sc1; o[j][3] *= sc1;
        }

        // ---- O += P V (P single fp16 plane, V single plane)
        #pragma unroll
        for (int kc = 0; kc < 4; kc++) {
            unsigned ph[4];
            ph[0] = pack2(sreg[2 * kc][0],     sreg[2 * kc][1]);
            ph[1] = pack2(sreg[2 * kc][2],     sreg[2 * kc][3]);
            ph[2] = pack2(sreg[2 * kc + 1][0], sreg[2 * kc + 1][1]);
            ph[3] = pack2(sreg[2 * kc + 1][2], sreg[2 * kc + 1][3]);
            #pragma unroll
            for (int t = 0; t < 4; t++) {
                unsigned bh[4];
                ldmx4t(bh, aVh + kc * 2304 + t * 32);
                mma16816(o[2 * t],     ph, bh);
                mma16816(o[2 * t + 1], ph, bh + 2);
            }
        }

        __syncthreads();   // all warps done with stage `stg` before reuse
        stg ^= 1;
    }

    const int row_lo = q0 + 16 * w + g;
    const int row_hi = row_lo + 8;
    const size_t sb  = (size_t)(b * NS + s) * SEQ;
    #pragma unroll
    for (int j = 0; j < 8; j++) {
        int col = 8 * j + 2 * cq;
        *(float2*)(g_Om + (sb + row_lo) * ADIM + col) = make_float2(o[j][0], o[j][1]);
        *(float2*)(g_Om + (sb + row_hi) * ADIM + col) = make_float2(o[j][2], o[j][3]);
    }
    if (cq == 0) {
        g_m[sb + row_lo] = m_lo;  g_l[sb + row_lo] = l_lo;
        g_m[sb + row_hi] = m_hi;  g_l[sb + row_hi] = l_hi;
    }
}

// ---------------------------------------------------------------------------
// Combine split-KV partials.
// ---------------------------------------------------------------------------
__global__ __launch_bounds__(128)
void combine_kernel(float* __restrict__ out)
{
    const int tid = threadIdx.x;
    const int row = blockIdx.x * 8 + (tid >> 4);
    const int b   = blockIdx.y;
    const int c0  = (tid & 15) * 4;
    const int qi  = row >> 6;
    const int ns  = (qi + 1 < NS) ? (qi + 1) : NS;

    float m = -1e30f;
    #pragma unroll
    for (int s = 0; s < NS; s++)
        if (s < ns) m = fmaxf(m, g_m[(size_t)(b * NS + s) * SEQ + row]);

    float l = 0.f;
    float4 acc = make_float4(0.f, 0.f, 0.f, 0.f);
    #pragma unroll
    for (int s = 0; s < NS; s++) {
        if (s >= ns) break;
        size_t sb = (size_t)(b * NS + s) * SEQ + row;
        float wgt = __expf(g_m[sb] - m);
        l += g_l[sb] * wgt;
        float4 v = *(const float4*)(g_Om + sb * ADIM + c0);
        acc.x += v.x * wgt; acc.y += v.y * wgt;
        acc.z += v.z * wgt; acc.w += v.w * wgt;
    }
    float inv = 1.f / l;
    float4 r;
    r.x = rintf(acc.x * inv * 1e4f) * 1e-4f;
    r.y = rintf(acc.y * inv * 1e4f) * 1e-4f;
    r.z = rintf(acc.z * inv * 1e4f) * 1e-4f;
    r.w = rintf(acc.w * inv * 1e4f) * 1e-4f;
    *(float4*)(out + ((size_t)b * SEQ + row) * ADIM + c0) = r;
}

extern "C" void kernel_launch(void* const* d_in, const int* in_sizes, int n_in,
                              void* d_out, int out_size)
{
    const float* x  = (const float*)d_in[0];
    const float* wk = (const float*)d_in[1];
    const float* wq = (const float*)d_in[2];
    const float* wv = (const float*)d_in[3];
    float* out = (float*)d_out;

    cudaFuncSetAttribute(qkv_proj, cudaFuncAttributeMaxDynamicSharedMemorySize, QP_SMEM);
    qkv_proj<<<256, 256, QP_SMEM>>>(x, wk, wq, wv);

    cudaFuncSetAttribute(attn_kernel, cudaFuncAttributeMaxDynamicSharedMemorySize, SMEM_ATTN);
    attn_kernel<<<dim3((SEQ / 64) * NS, NB), 128, SMEM_ATTN>>>();

    combine_kernel<<<dim3(SEQ / 8, NB), 128>>>(out);
}